// round 6
// baseline (speedup 1.0000x reference)
#include <cuda_runtime.h>
#include <math.h>

#define Bc 16
#define Nc 16384
#define Kc 8
#define DIMc 256
#define Hc 4
#define DHc 64
#define EPSc 1e-8f
#define SCALEc 0.125f

// ---------------- scratch (static device globals; no allocation) ----------------
__device__ float g_k[(size_t)Bc * Nc * DIMc];      // 256 MB
__device__ float g_v[(size_t)Bc * Nc * DIMc];      // 256 MB
__device__ float g_Wg[512 * 256];                  // folded [k;v] weights * ln_in_g
__device__ float g_s1[512];
__device__ float g_s2[512];
__device__ float g_q[128 * 256];                   // [b*8+i][h*64+d]
__device__ float g_S[16 * 32];                     // attn row sums [b][i*4+h]
__device__ float g_upd[128 * 256];
__device__ float g_vsum[16 * 256];                 // sum_n v[b,n,:]
__device__ float g_slots[128 * 256];
__device__ float g_ff[128 * 1024];
__device__ float g_x[128 * 256];                   // LN staging
__device__ float g_gi[128 * 768];
__device__ float g_gh[128 * 768];

__device__ __forceinline__ float sigmoidf_(float x) { return 1.0f / (1.0f + expf(-x)); }
__device__ __forceinline__ float geluf_(float x) {
    return 0.5f * x * (1.0f + erff(x * 0.70710678118654752f));
}

// fast exp via FMA-pipe (2^f Taylor deg-6), rel err ~1.5e-5, valid for x <= 0
__device__ __forceinline__ float fexp(float x) {
    x = fmaxf(x, -87.0f);
    float y = x * 1.4426950408889634f;
    float fy = floorf(y);
    float f = y - fy;
    float p = 1.5403530393e-4f;
    p = p * f + 1.3333558146e-3f;
    p = p * f + 9.6181291076e-3f;
    p = p * f + 5.5504108665e-2f;
    p = p * f + 2.4022650696e-1f;
    p = p * f + 6.9314718056e-1f;
    p = p * f + 1.0f;
    int e = (int)fy;
    return p * __int_as_float((e + 127) << 23);
}

__device__ __forceinline__ unsigned cvt_tf32(float f) {
    unsigned r;
    asm("cvt.rna.tf32.f32 %0, %1;" : "=r"(r) : "f"(f));
    return r;
}

__device__ __forceinline__ void mma_tf32(float c[4], const unsigned a[4], const unsigned b[2]) {
    asm volatile(
        "mma.sync.aligned.m16n8k8.row.col.f32.tf32.tf32.f32 "
        "{%0,%1,%2,%3},{%4,%5,%6,%7},{%8,%9},{%0,%1,%2,%3};"
        : "+f"(c[0]), "+f"(c[1]), "+f"(c[2]), "+f"(c[3])
        : "r"(a[0]), "r"(a[1]), "r"(a[2]), "r"(a[3]), "r"(b[0]), "r"(b[1]));
}

// ---------------- prep: fold ln_in gamma/beta into K/V weights ----------------
__global__ void prep_fold(const float* __restrict__ wk, const float* __restrict__ wv,
                          const float* __restrict__ g, const float* __restrict__ b) {
    int j = blockIdx.x;           // 0..511
    int c = threadIdx.x;          // 0..255
    const float* W = (j < 256) ? (wk + (size_t)j * 256) : (wv + (size_t)(j - 256) * 256);
    float w = W[c];
    float wg = w * g[c];
    float wb = w * b[c];
    g_Wg[j * 256 + c] = wg;
    __shared__ float r1[8], r2[8];
    float a = wg, bb = wb;
#pragma unroll
    for (int o = 16; o; o >>= 1) {
        a += __shfl_xor_sync(0xffffffffu, a, o);
        bb += __shfl_xor_sync(0xffffffffu, bb, o);
    }
    if ((c & 31) == 0) { r1[c >> 5] = a; r2[c >> 5] = bb; }
    __syncthreads();
    if (c == 0) {
        float s1 = 0.f, s2 = 0.f;
#pragma unroll
        for (int u = 0; u < 8; u++) { s1 += r1[u]; s2 += r2[u]; }
        g_s1[j] = s1; g_s2[j] = s2;
    }
}

// ---------------- big GEMM: C[M,256] per column-half ; BM=128 BN=256 BK=32 ----------
// grid (2, 2048), 512 threads = 16 warps (4m x 4n), warp tile 32x64
#define GPAD 36
__global__ __launch_bounds__(512) void kv_gemm_tc(const float* __restrict__ x) {
    extern __shared__ char smraw[];
    unsigned* As = (unsigned*)smraw;                    // 128*GPAD
    unsigned* Bs = As + 128 * GPAD;                     // 256*GPAD
    float* mu_s = (float*)(Bs + 256 * GPAD);            // 128
    float* rs_s = mu_s + 128;                           // 128
    const int tid = threadIdx.x;
    const int wid = tid >> 5, lane = tid & 31;
    const int g = lane >> 2, tig = lane & 3;
    const int wm = (wid & 3) * 32, wn = (wid >> 2) * 64;
    const int bm = blockIdx.y * 128;
    const int bnsel = blockIdx.x;                        // 0 = K cols, 1 = V cols

    float c[2][8][4];
#pragma unroll
    for (int mt = 0; mt < 2; mt++)
#pragma unroll
        for (int nt = 0; nt < 8; nt++)
#pragma unroll
            for (int e = 0; e < 4; e++) c[mt][nt][e] = 0.f;

    float ss[2] = {0, 0}, ss2[2] = {0, 0};

    float4 areg[2], breg[4];
#pragma unroll
    for (int u = 0; u < 2; u++) {
        int l = u * 512 + tid;
        areg[u] = *(const float4*)&x[(size_t)(bm + (l >> 3)) * 256 + (l & 7) * 4];
    }
#pragma unroll
    for (int u = 0; u < 4; u++) {
        int l = u * 512 + tid;
        breg[u] = *(const float4*)&g_Wg[(size_t)(bnsel * 256 + (l >> 3)) * 256 + (l & 7) * 4];
    }

    for (int iter = 0; iter < 8; iter++) {
#pragma unroll
        for (int u = 0; u < 2; u++) {
            int l = u * 512 + tid;
            float4 a = areg[u];
            ss[u] += a.x + a.y + a.z + a.w;
            ss2[u] += a.x * a.x + a.y * a.y + a.z * a.z + a.w * a.w;
            uint4 ta = make_uint4(cvt_tf32(a.x), cvt_tf32(a.y), cvt_tf32(a.z), cvt_tf32(a.w));
            *(uint4*)&As[(l >> 3) * GPAD + (l & 7) * 4] = ta;
        }
#pragma unroll
        for (int u = 0; u < 4; u++) {
            int l = u * 512 + tid;
            float4 b = breg[u];
            uint4 tb = make_uint4(cvt_tf32(b.x), cvt_tf32(b.y), cvt_tf32(b.z), cvt_tf32(b.w));
            *(uint4*)&Bs[(l >> 3) * GPAD + (l & 7) * 4] = tb;
        }
        __syncthreads();
        if (iter < 7) {
            int k0 = (iter + 1) * 32;
#pragma unroll
            for (int u = 0; u < 2; u++) {
                int l = u * 512 + tid;
                areg[u] = *(const float4*)&x[(size_t)(bm + (l >> 3)) * 256 + k0 + (l & 7) * 4];
            }
#pragma unroll
            for (int u = 0; u < 4; u++) {
                int l = u * 512 + tid;
                breg[u] = *(const float4*)&g_Wg[(size_t)(bnsel * 256 + (l >> 3)) * 256 + k0 +
                                                (l & 7) * 4];
            }
        }
#pragma unroll
        for (int kk = 0; kk < 32; kk += 8) {
            unsigned af[2][4];
#pragma unroll
            for (int mt = 0; mt < 2; mt++) {
                int mr = wm + mt * 16;
                af[mt][0] = As[(mr + g) * GPAD + kk + tig];
                af[mt][1] = As[(mr + 8 + g) * GPAD + kk + tig];
                af[mt][2] = As[(mr + g) * GPAD + kk + tig + 4];
                af[mt][3] = As[(mr + 8 + g) * GPAD + kk + tig + 4];
            }
            unsigned bf[8][2];
#pragma unroll
            for (int nt = 0; nt < 8; nt++) {
                int nr = wn + nt * 8;
                bf[nt][0] = Bs[(nr + g) * GPAD + kk + tig];
                bf[nt][1] = Bs[(nr + g) * GPAD + kk + tig + 4];
            }
#pragma unroll
            for (int mt = 0; mt < 2; mt++)
#pragma unroll
                for (int nt = 0; nt < 8; nt++) mma_tf32(c[mt][nt], af[mt], bf[nt]);
        }
        __syncthreads();
    }

    // finalize row stats (8 lanes share each row)
#pragma unroll
    for (int o = 1; o < 8; o <<= 1) {
#pragma unroll
        for (int u = 0; u < 2; u++) {
            ss[u] += __shfl_xor_sync(0xffffffffu, ss[u], o);
            ss2[u] += __shfl_xor_sync(0xffffffffu, ss2[u], o);
        }
    }
    if ((tid & 7) == 0) {
#pragma unroll
        for (int u = 0; u < 2; u++) {
            int r = (u * 512 + tid) >> 3;
            float m = ss[u] * (1.0f / 256.0f);
            float var = ss2[u] * (1.0f / 256.0f) - m * m;
            mu_s[r] = m;
            rs_s[r] = rsqrtf(var + 1e-5f);
        }
    }
    __syncthreads();

    float* dst = bnsel ? g_v : g_k;
#pragma unroll
    for (int nt = 0; nt < 8; nt++) {
        int cl = wn + nt * 8 + tig * 2;                 // local col 0..255
        int colg = bnsel * 256 + cl;                    // global 0..511
        float2 s1v = *(const float2*)&g_s1[colg];
        float2 s2v = *(const float2*)&g_s2[colg];
#pragma unroll
        for (int mt = 0; mt < 2; mt++) {
            int lr0 = wm + mt * 16 + g;
            int r0 = bm + lr0;
            float mu0 = mu_s[lr0], rs0 = rs_s[lr0];
            float mu1 = mu_s[lr0 + 8], rs1 = rs_s[lr0 + 8];
            float2 o0, o1;
            o0.x = rs0 * (c[mt][nt][0] - mu0 * s1v.x) + s2v.x;
            o0.y = rs0 * (c[mt][nt][1] - mu0 * s1v.y) + s2v.y;
            o1.x = rs1 * (c[mt][nt][2] - mu1 * s1v.x) + s2v.x;
            o1.y = rs1 * (c[mt][nt][3] - mu1 * s1v.y) + s2v.y;
            *(float2*)&dst[(size_t)r0 * 256 + cl] = o0;
            *(float2*)&dst[(size_t)(r0 + 8) * 256 + cl] = o1;
        }
    }
}

// ---------------- Vsum[b,c] = sum_n v[b,n,c] (once) ----------------
__global__ void vsum_kernel() {
    int b = blockIdx.x, ch = blockIdx.y;
    int c = threadIdx.x;
    const float* vp = &g_v[((size_t)b * Nc + ch * 1024) * 256 + c];
    float a0 = 0.f, a1 = 0.f, a2 = 0.f, a3 = 0.f;
    for (int r = 0; r < 1024; r += 4) {
        a0 += vp[(size_t)(r + 0) * 256];
        a1 += vp[(size_t)(r + 1) * 256];
        a2 += vp[(size_t)(r + 2) * 256];
        a3 += vp[(size_t)(r + 3) * 256];
    }
    atomicAdd(&g_vsum[b * 256 + c], a0 + a1 + a2 + a3);
}

// ---------------- LN over 128 rows of 256 (fp32) ----------------
__global__ void ln_rows(const float* __restrict__ in, const float* __restrict__ g,
                        const float* __restrict__ b, float* __restrict__ outp) {
    int row = blockIdx.x;
    int lane = threadIdx.x;
    const float* xr = &in[row * 256];
    float v[8];
    float s = 0.f, s2 = 0.f;
#pragma unroll
    for (int u = 0; u < 8; u++) {
        v[u] = xr[lane + u * 32];
        s += v[u]; s2 += v[u] * v[u];
    }
#pragma unroll
    for (int o = 16; o; o >>= 1) {
        s += __shfl_xor_sync(0xffffffffu, s, o);
        s2 += __shfl_xor_sync(0xffffffffu, s2, o);
    }
    float m = s * (1.0f / 256.0f);
    float var = s2 * (1.0f / 256.0f) - m * m;
    float rs = rsqrtf(var + 1e-5f);
#pragma unroll
    for (int u = 0; u < 8; u++) {
        int cc = lane + u * 32;
        outp[row * 256 + cc] = (v[u] - m) * rs * g[cc] + b[cc];
    }
}

// ---------------- skinny GEMM: one output column per block ----------------
// MODE: 0 = plain, 1 = gelu, 2 = residual add
template<int K, int MODE>
__global__ __launch_bounds__(128) void colgemm(const float* __restrict__ X,
                                               const float* __restrict__ W,
                                               const float* __restrict__ bias,
                                               float* __restrict__ out, int ostride,
                                               const float* __restrict__ resid) {
    constexpr int KL = K / 32;
    constexpr int RPB = (K == 256) ? 4 : 2;
    const int j0 = blockIdx.x;
    const int w = threadIdx.x >> 5, lane = threadIdx.x & 31;

    float wf[KL];
    const float* wp = &W[(size_t)j0 * K + lane * KL];
#pragma unroll
    for (int u = 0; u < KL; u += 4) *(float4*)&wf[u] = *(const float4*)&wp[u];
    float b0 = bias ? bias[j0] : 0.f;

    for (int r0 = w * 32; r0 < w * 32 + 32; r0 += RPB) {
        float xf[RPB][KL];
#pragma unroll
        for (int rr = 0; rr < RPB; rr++)
#pragma unroll
            for (int u = 0; u < KL; u += 4)
                *(float4*)&xf[rr][u] =
                    *(const float4*)&X[(size_t)(r0 + rr) * K + lane * KL + u];
        float a[RPB];
#pragma unroll
        for (int rr = 0; rr < RPB; rr++) {
            a[rr] = 0.f;
#pragma unroll
            for (int u = 0; u < KL; u++) a[rr] += xf[rr][u] * wf[u];
        }
#pragma unroll
        for (int o = 16; o; o >>= 1)
#pragma unroll
            for (int rr = 0; rr < RPB; rr++)
                a[rr] += __shfl_xor_sync(0xffffffffu, a[rr], o);
        if (lane == 0) {
#pragma unroll
            for (int rr = 0; rr < RPB; rr++) {
                int row = r0 + rr;
                float v0 = a[rr] + b0;
                if (MODE == 1) v0 = geluf_(v0);
                if (MODE == 2) v0 += resid[(size_t)row * ostride + j0];
                out[(size_t)row * ostride + j0] = v0;
            }
        }
    }
}

// ---------------- GRU combine (elementwise) ----------------
__global__ void gru_combine() {
    int row = blockIdx.x;
    int j = threadIdx.x;
    float gir = g_gi[row * 768 + j], giz = g_gi[row * 768 + 256 + j],
          gin = g_gi[row * 768 + 512 + j];
    float ghr = g_gh[row * 768 + j], ghz = g_gh[row * 768 + 256 + j],
          ghn = g_gh[row * 768 + 512 + j];
    float h = g_slots[row * 256 + j];
    float r = sigmoidf_(gir + ghr);
    float z = sigmoidf_(giz + ghz);
    float n = tanhf(gin + r * ghn);
    g_slots[row * 256 + j] = (1.0f - z) * n + z * h;
}

// ---------------- fused attention: dots + inverted softmax + U/S accumulation -------
// grid (32, 16) : chunk of 512 n, batch b. 256 threads.
// phase A: thread = (n_l 0..31, i 0..7) computes 4-head dots + softmax for one n row
// phase B: thread = (h 0..3, d 0..63) accumulates U[i] = sum_n attn * v
__global__ __launch_bounds__(256) void attn_fused(float* __restrict__ ao) {
    extern __shared__ float sm[];
    float* ks = sm;                 // 32*260
    float* vs = ks + 32 * 260;      // 32*260
    float* qs = vs + 32 * 260;      // 8*260
    float* at = qs + 8 * 260;       // 32*36
    float* sp = at + 32 * 36;       // 32*32

    const int b = blockIdx.y;
    const int n0 = blockIdx.x * 512;
    const int t = threadIdx.x;
    const int n_l = t >> 3, i = t & 7;
    const int h_b = t >> 6, d_b = t & 63;

#pragma unroll
    for (int u = 0; u < 2; u++) {
        int l = u * 256 + t;
        int qi = l >> 6, c4 = l & 63;
        *(float4*)&qs[qi * 260 + c4 * 4] = *(const float4*)&g_q[(b * 8 + qi) * 256 + c4 * 4];
    }

    float U[8] = {0, 0, 0, 0, 0, 0, 0, 0};
    float sacc[4] = {0, 0, 0, 0};

    for (int tile = 0; tile < 16; tile++) {
        int nt = n0 + tile * 32;
        __syncthreads();
#pragma unroll
        for (int u = 0; u < 8; u++) {
            int l = u * 256 + t;
            int r = l >> 6, c4 = l & 63;
            *(float4*)&ks[r * 260 + c4 * 4] =
                *(const float4*)&g_k[((size_t)b * Nc + nt + r) * 256 + c4 * 4];
            *(float4*)&vs[r * 260 + c4 * 4] =
                *(const float4*)&g_v[((size_t)b * Nc + nt + r) * 256 + c4 * 4];
        }
        __syncthreads();

        // phase A: dots + softmax for row n_l, slot i, heads 0..3
        float dot[4] = {0, 0, 0, 0};
#pragma unroll
        for (int d4 = 0; d4 < 64; d4++) {
            float4 kk = *(float4*)&ks[n_l * 260 + d4 * 4];
            float4 qq = *(float4*)&qs[i * 260 + d4 * 4];
            int h = d4 >> 4;
            dot[h] += kk.x * qq.x + kk.y * qq.y + kk.z * qq.z + kk.w * qq.w;
        }
        float d0 = dot[0] * SCALEc, d1 = dot[1] * SCALEc;
        float d2 = dot[2] * SCALEc, d3 = dot[3] * SCALEc;
        float m = fmaxf(fmaxf(d0, d1), fmaxf(d2, d3));
#pragma unroll
        for (int o = 1; o < 8; o <<= 1) m = fmaxf(m, __shfl_xor_sync(0xffffffffu, m, o));
        float e0 = fexp(d0 - m), e1 = fexp(d1 - m);
        float e2 = fexp(d2 - m), e3 = fexp(d3 - m);
        float s = e0 + e1 + e2 + e3;
#pragma unroll
        for (int o = 1; o < 8; o <<= 1) s += __shfl_xor_sync(0xffffffffu, s, o);
        float inv = 1.0f / s;
        float a0 = e0 * inv, a1 = e1 * inv, a2 = e2 * inv, a3 = e3 * inv;
        at[n_l * 36 + 0 * 8 + i] = a0;
        at[n_l * 36 + 1 * 8 + i] = a1;
        at[n_l * 36 + 2 * 8 + i] = a2;
        at[n_l * 36 + 3 * 8 + i] = a3;
        sacc[0] += a0; sacc[1] += a1; sacc[2] += a2; sacc[3] += a3;
        if (ao) ao[(size_t)(b * 8 + i) * Nc + nt + n_l] = (a0 + a1 + a2 + a3) * 0.25f;
        __syncthreads();

        // phase B: U[i] += attn[n, h_b*8+i] * v[n, h_b*64+d_b]
#pragma unroll 4
        for (int n = 0; n < 32; n++) {
            float4 A0 = *(float4*)&at[n * 36 + h_b * 8];
            float4 A1 = *(float4*)&at[n * 36 + h_b * 8 + 4];
            float vv = vs[n * 260 + h_b * 64 + d_b];
            U[0] += A0.x * vv; U[1] += A0.y * vv; U[2] += A0.z * vv; U[3] += A0.w * vv;
            U[4] += A1.x * vv; U[5] += A1.y * vv; U[6] += A1.z * vv; U[7] += A1.w * vv;
        }
    }

    // S reduction
#pragma unroll
    for (int h = 0; h < 4; h++) sp[n_l * 32 + i * 4 + h] = sacc[h];
    __syncthreads();
    if (t < 32) {
        float s = 0.f;
#pragma unroll
        for (int nl = 0; nl < 32; nl++) s += sp[nl * 32 + t];
        atomicAdd(&g_S[b * 32 + t], s);
    }
    // U atomics
#pragma unroll
    for (int ii = 0; ii < 8; ii++)
        atomicAdd(&g_upd[(b * 8 + ii) * 256 + h_b * 64 + d_b], U[ii]);
}

// ---------------- normalize updates: upd = (U + EPS*Vsum) / (S + EPS) ----------------
__global__ void normalize_upd() {
    int row = blockIdx.x;      // b*8+i
    int c = threadIdx.x;       // h*64+d
    int b = row >> 3, i = row & 7, h = c >> 6;
    float u = g_upd[row * 256 + c];
    float vsm = g_vsum[b * 256 + c];
    float S = g_S[b * 32 + i * 4 + h];
    g_upd[row * 256 + c] = (u + EPSc * vsm) / (S + EPSc);
}

// ---------------- host ----------------
extern "C" void kernel_launch(void* const* d_in, const int* in_sizes, int n_in,
                              void* d_out, int out_size) {
    const float* inputs = (const float*)d_in[0];
    const float* slots0 = (const float*)d_in[1];
    const float* w_q = (const float*)d_in[2];
    const float* w_k = (const float*)d_in[3];
    const float* w_v = (const float*)d_in[4];
    const float* w_ih = (const float*)d_in[5];
    const float* w_hh = (const float*)d_in[6];
    const float* b_ih = (const float*)d_in[7];
    const float* b_hh = (const float*)d_in[8];
    const float* ln_in_g = (const float*)d_in[9];
    const float* ln_in_b = (const float*)d_in[10];
    const float* ln_s_g = (const float*)d_in[11];
    const float* ln_s_b = (const float*)d_in[12];
    const float* ln_ff_g = (const float*)d_in[13];
    const float* ln_ff_b = (const float*)d_in[14];
    const float* w_ff1 = (const float*)d_in[15];
    const float* b_ff1 = (const float*)d_in[16];
    const float* w_ff2 = (const float*)d_in[17];
    const float* b_ff2 = (const float*)d_in[18];
    float* out = (float*)d_out;

    void *slots_dev, *S_dev, *upd_dev, *x_dev, *q_dev, *gi_dev, *gh_dev, *ff_dev, *vs_dev;
    cudaGetSymbolAddress(&slots_dev, g_slots);
    cudaGetSymbolAddress(&S_dev, g_S);
    cudaGetSymbolAddress(&upd_dev, g_upd);
    cudaGetSymbolAddress(&x_dev, g_x);
    cudaGetSymbolAddress(&q_dev, g_q);
    cudaGetSymbolAddress(&gi_dev, g_gi);
    cudaGetSymbolAddress(&gh_dev, g_gh);
    cudaGetSymbolAddress(&ff_dev, g_ff);
    cudaGetSymbolAddress(&vs_dev, g_vsum);
    float* slots = (float*)slots_dev;
    float* xbuf = (float*)x_dev;
    float* qbuf = (float*)q_dev;
    float* updb = (float*)upd_dev;
    float* gib = (float*)gi_dev;
    float* ghb = (float*)gh_dev;
    float* ffb = (float*)ff_dev;

    const int kv_smem = (128 * GPAD + 256 * GPAD) * 4 + 256 * 4;
    const int at_smem = (32 * 260 * 2 + 8 * 260 + 32 * 36 + 32 * 32) * 4;
    cudaFuncSetAttribute(kv_gemm_tc, cudaFuncAttributeMaxDynamicSharedMemorySize, kv_smem);
    cudaFuncSetAttribute(attn_fused, cudaFuncAttributeMaxDynamicSharedMemorySize, at_smem);

    cudaMemcpyAsync(slots_dev, slots0, 128 * 256 * sizeof(float), cudaMemcpyDeviceToDevice);
    prep_fold<<<512, 256>>>(w_k, w_v, ln_in_g, ln_in_b);
    kv_gemm_tc<<<dim3(2, (Bc * Nc) / 128), 512, kv_smem>>>(inputs);
    cudaMemsetAsync(vs_dev, 0, 16 * 256 * sizeof(float));
    vsum_kernel<<<dim3(16, 16), 256>>>();

    for (int it = 0; it < 3; it++) {
        ln_rows<<<128, 32>>>(slots, ln_s_g, ln_s_b, xbuf);
        colgemm<256, 0><<<256, 128>>>(xbuf, w_q, (const float*)0, qbuf, 256, (const float*)0);
        cudaMemsetAsync(S_dev, 0, 16 * 32 * sizeof(float));
        cudaMemsetAsync(upd_dev, 0, 128 * 256 * sizeof(float));
        attn_fused<<<dim3(32, 16), 256, at_smem>>>((it == 2) ? (out + 128 * 256) : (float*)0);
        normalize_upd<<<128, 256>>>();
        colgemm<256, 0><<<768, 128>>>(updb, w_ih, b_ih, gib, 768, (const float*)0);
        colgemm<256, 0><<<768, 128>>>(slots, w_hh, b_hh, ghb, 768, (const float*)0);
        gru_combine<<<128, 256>>>();
        ln_rows<<<128, 32>>>(slots, ln_ff_g, ln_ff_b, xbuf);
        colgemm<256, 1><<<1024, 128>>>(xbuf, w_ff1, b_ff1, ffb, 1024, (const float*)0);
        colgemm<1024, 2><<<256, 128>>>(ffb, w_ff2, b_ff2, slots, 256, slots);
    }
    cudaMemcpyAsync(d_out, slots_dev, 128 * 256 * sizeof(float), cudaMemcpyDeviceToDevice);
}